// round 1
// baseline (speedup 1.0000x reference)
#include <cuda_runtime.h>
#include <cuda_bf16.h>
#include <math.h>

#define NN 50000
#define EE 800000
#define E2 (EE + NN)      // edges + self loops
#define HID 128
#define HEADS 4
#define OUTC 64
#define DEPTH 4
#define FEPS 1e-6f
#define NEG_SLOPE 0.2f

// ---------------- device scratch (static; no allocation allowed) ----------------
__device__ float g_h[(size_t)NN * HID];          // 25.6 MB
__device__ float g_ln[(size_t)NN * HID];         // 25.6 MB
__device__ float g_xh[(size_t)NN * HEADS * HID]; // 102.4 MB
__device__ float g_as[(size_t)NN * HEADS];
__device__ float g_ad[(size_t)NN * HEADS];
__device__ int   g_cnt[NN];
__device__ int   g_rowptr[NN + 1];
__device__ int   g_wp[NN];
__device__ int   g_src[E2];

// ---------------- CSR build ----------------
__global__ void k_zero_cnt() {
    int i = blockIdx.x * blockDim.x + threadIdx.x;
    if (i < NN) g_cnt[i] = 0;
}

__device__ __forceinline__ int edge_src(const int* ei, int e) {
    return (e < EE) ? ei[e] : (e - EE);
}
__device__ __forceinline__ int edge_dst(const int* ei, int e) {
    return (e < EE) ? ei[EE + e] : (e - EE);
}

__global__ void k_count(const int* __restrict__ ei) {
    int e = blockIdx.x * blockDim.x + threadIdx.x;
    if (e < E2) atomicAdd(&g_cnt[edge_dst(ei, e)], 1);
}

__global__ void k_scan() {  // 1 block, 1024 threads
    __shared__ int sh[1024];
    __shared__ int carry;
    int tid = threadIdx.x;
    if (tid == 0) carry = 0;
    __syncthreads();
    for (int base = 0; base < NN; base += 1024) {
        int i = base + tid;
        int v = (i < NN) ? g_cnt[i] : 0;
        sh[tid] = v;
        __syncthreads();
        for (int off = 1; off < 1024; off <<= 1) {
            int t = (tid >= off) ? sh[tid - off] : 0;
            __syncthreads();
            sh[tid] += t;
            __syncthreads();
        }
        int excl = sh[tid] - v;
        if (i < NN) { g_rowptr[i] = carry + excl; g_wp[i] = carry + excl; }
        __syncthreads();
        if (tid == 1023) carry += sh[1023];
        __syncthreads();
    }
    if (tid == 0) g_rowptr[NN] = carry;
}

__global__ void k_fill(const int* __restrict__ ei) {
    int e = blockIdx.x * blockDim.x + threadIdx.x;
    if (e < E2) {
        int d = edge_dst(ei, e);
        int s = edge_src(ei, e);
        int pos = atomicAdd(&g_wp[d], 1);
        g_src[pos] = s;
    }
}

// ---------------- input projection ----------------
__global__ void k_in_proj(const float* __restrict__ x, const float* __restrict__ Win,
                          const float* __restrict__ bin) {
    int i = blockIdx.x * blockDim.x + threadIdx.x;
    if (i >= NN * HID) return;
    int n = i >> 7, c = i & 127;
    float x0 = x[n * 3 + 0], x1 = x[n * 3 + 1], x2 = x[n * 3 + 2];
    g_h[i] = x0 * Win[c] + x1 * Win[HID + c] + x2 * Win[2 * HID + c] + bin[c];
}

// ---------------- layer norm ----------------
__global__ void k_ln(const float* __restrict__ gamma, const float* __restrict__ beta) {
    int row = blockIdx.x * 4 + threadIdx.y;
    if (row >= NN) return;
    int lane = threadIdx.x;
    const float* hr = g_h + (size_t)row * HID;
    float v0 = hr[lane], v1 = hr[lane + 32], v2 = hr[lane + 64], v3 = hr[lane + 96];
    float s = v0 + v1 + v2 + v3;
#pragma unroll
    for (int o = 16; o; o >>= 1) s += __shfl_xor_sync(0xffffffffu, s, o);
    float mu = s * (1.0f / 128.0f);
    float d0 = v0 - mu, d1 = v1 - mu, d2 = v2 - mu, d3 = v3 - mu;
    float q = d0 * d0 + d1 * d1 + d2 * d2 + d3 * d3;
#pragma unroll
    for (int o = 16; o; o >>= 1) q += __shfl_xor_sync(0xffffffffu, q, o);
    float inv = rsqrtf(q * (1.0f / 128.0f) + FEPS);
    float* lr = g_ln + (size_t)row * HID;
    lr[lane]      = d0 * inv * gamma[lane]      + beta[lane];
    lr[lane + 32] = d1 * inv * gamma[lane + 32] + beta[lane + 32];
    lr[lane + 64] = d2 * inv * gamma[lane + 64] + beta[lane + 64];
    lr[lane + 96] = d3 * inv * gamma[lane + 96] + beta[lane + 96];
}

// ---------------- GEMM: ln[N,128] @ W[128,512] -> xh[N,512] ----------------
#define BM 128
#define BN 64
#define BK 32
__global__ void k_gemm(const float* __restrict__ W) {
    __shared__ float As[BM * BK];
    __shared__ float Bs[BK * BN];
    int tid = threadIdx.x;                 // 256 threads
    int row0 = blockIdx.y * BM;
    int col0 = blockIdx.x * BN;
    int tx = tid & 15, ty = tid >> 4;
    float acc[8][4];
#pragma unroll
    for (int i = 0; i < 8; i++)
#pragma unroll
        for (int j = 0; j < 4; j++) acc[i][j] = 0.0f;

    for (int k0 = 0; k0 < 128; k0 += BK) {
#pragma unroll
        for (int l = 0; l < 4; l++) {
            int lin = (tid + l * 256) * 4;
            int r = lin / BK, kk = lin % BK;
            float4 v = make_float4(0.f, 0.f, 0.f, 0.f);
            if (row0 + r < NN)
                v = *(const float4*)(g_ln + (size_t)(row0 + r) * 128 + k0 + kk);
            *(float4*)(As + lin) = v;
        }
#pragma unroll
        for (int l = 0; l < 2; l++) {
            int lin = (tid + l * 256) * 4;
            int r = lin / BN, cc = lin % BN;
            *(float4*)(Bs + lin) = *(const float4*)(W + (size_t)(k0 + r) * 512 + col0 + cc);
        }
        __syncthreads();
#pragma unroll
        for (int kk = 0; kk < BK; kk++) {
            float b[4];
            *(float4*)b = *(float4*)(Bs + kk * BN + tx * 4);
            float a[8];
#pragma unroll
            for (int i = 0; i < 8; i++) a[i] = As[(ty * 8 + i) * BK + kk];
#pragma unroll
            for (int i = 0; i < 8; i++)
#pragma unroll
                for (int j = 0; j < 4; j++) acc[i][j] += a[i] * b[j];
        }
        __syncthreads();
    }
#pragma unroll
    for (int i = 0; i < 8; i++) {
        int r = row0 + ty * 8 + i;
        if (r < NN) {
            float4 v = make_float4(acc[i][0], acc[i][1], acc[i][2], acc[i][3]);
            *(float4*)(g_xh + (size_t)r * 512 + col0 + tx * 4) = v;
        }
    }
}

// ---------------- attention scalars: as[n,h], ad[n,h] ----------------
__global__ void k_attn(const float* __restrict__ asrc, const float* __restrict__ adst) {
    int n = blockIdx.x;
    int w = threadIdx.x >> 5, lane = threadIdx.x & 31;
    const float* xr = g_xh + (size_t)n * 512 + w * 128;
    const float* av = asrc + w * 128;
    const float* dv = adst + w * 128;
    float sa = 0.f, sd = 0.f;
#pragma unroll
    for (int c = lane; c < 128; c += 32) {
        float x = xr[c];
        sa += x * av[c];
        sd += x * dv[c];
    }
#pragma unroll
    for (int o = 16; o; o >>= 1) {
        sa += __shfl_xor_sync(0xffffffffu, sa, o);
        sd += __shfl_xor_sync(0xffffffffu, sd, o);
    }
    if (lane == 0) { g_as[n * 4 + w] = sa; g_ad[n * 4 + w] = sd; }
}

// ---------------- aggregation: softmax + weighted gather + mean + bias + relu + residual ----------------
#define CHUNK 256
__device__ __forceinline__ float lrelu(float x) { return x > 0.f ? x : NEG_SLOPE * x; }

__global__ void k_agg(const float* __restrict__ bconv) {
    int n = blockIdx.x;
    int t = threadIdx.x;                 // 128 threads
    int w = t >> 5, lane = t & 31;
    int beg = g_rowptr[n], end = g_rowptr[n + 1];

    __shared__ float s_m[4], s_z[4];
    __shared__ float red[4][4];
    __shared__ float4 s_w[CHUNK];
    __shared__ int   s_src[CHUNK];

    float4 adv = *(const float4*)(g_ad + (size_t)n * 4);

    // pass 1: per-head max
    float m0 = -INFINITY, m1 = -INFINITY, m2 = -INFINITY, m3 = -INFINITY;
    for (int k = beg + t; k < end; k += 128) {
        int s = g_src[k];
        float4 a = *(const float4*)(g_as + (size_t)s * 4);
        m0 = fmaxf(m0, lrelu(a.x + adv.x));
        m1 = fmaxf(m1, lrelu(a.y + adv.y));
        m2 = fmaxf(m2, lrelu(a.z + adv.z));
        m3 = fmaxf(m3, lrelu(a.w + adv.w));
    }
#pragma unroll
    for (int o = 16; o; o >>= 1) {
        m0 = fmaxf(m0, __shfl_xor_sync(0xffffffffu, m0, o));
        m1 = fmaxf(m1, __shfl_xor_sync(0xffffffffu, m1, o));
        m2 = fmaxf(m2, __shfl_xor_sync(0xffffffffu, m2, o));
        m3 = fmaxf(m3, __shfl_xor_sync(0xffffffffu, m3, o));
    }
    if (lane == 0) { red[w][0] = m0; red[w][1] = m1; red[w][2] = m2; red[w][3] = m3; }
    __syncthreads();
    if (t == 0) {
#pragma unroll
        for (int h = 0; h < 4; h++)
            s_m[h] = fmaxf(fmaxf(red[0][h], red[1][h]), fmaxf(red[2][h], red[3][h]));
    }
    __syncthreads();
    float M0 = s_m[0], M1 = s_m[1], M2 = s_m[2], M3 = s_m[3];

    // pass 2: per-head sum of exp
    float z0 = 0.f, z1 = 0.f, z2 = 0.f, z3 = 0.f;
    for (int k = beg + t; k < end; k += 128) {
        int s = g_src[k];
        float4 a = *(const float4*)(g_as + (size_t)s * 4);
        z0 += __expf(lrelu(a.x + adv.x) - M0);
        z1 += __expf(lrelu(a.y + adv.y) - M1);
        z2 += __expf(lrelu(a.z + adv.z) - M2);
        z3 += __expf(lrelu(a.w + adv.w) - M3);
    }
#pragma unroll
    for (int o = 16; o; o >>= 1) {
        z0 += __shfl_xor_sync(0xffffffffu, z0, o);
        z1 += __shfl_xor_sync(0xffffffffu, z1, o);
        z2 += __shfl_xor_sync(0xffffffffu, z2, o);
        z3 += __shfl_xor_sync(0xffffffffu, z3, o);
    }
    __syncthreads();
    if (lane == 0) { red[w][0] = z0; red[w][1] = z1; red[w][2] = z2; red[w][3] = z3; }
    __syncthreads();
    if (t == 0) {
#pragma unroll
        for (int h = 0; h < 4; h++)
            s_z[h] = red[0][h] + red[1][h] + red[2][h] + red[3][h];
    }
    __syncthreads();

    // pass 3: weighted accumulation over edges, chunked through shared
    float acc0 = 0.f, acc1 = 0.f, acc2 = 0.f, acc3 = 0.f;
    int c = t;
    for (int cb = beg; cb < end; cb += CHUNK) {
        int ce = min(end, cb + CHUNK);
        for (int k = cb + t; k < ce; k += 128) {
            int s = g_src[k];
            float4 a = *(const float4*)(g_as + (size_t)s * 4);
            s_w[k - cb] = make_float4(__expf(lrelu(a.x + adv.x) - M0),
                                      __expf(lrelu(a.y + adv.y) - M1),
                                      __expf(lrelu(a.z + adv.z) - M2),
                                      __expf(lrelu(a.w + adv.w) - M3));
            s_src[k - cb] = s;
        }
        __syncthreads();
        int cnt = ce - cb;
        for (int k = 0; k < cnt; k++) {
            float4 wv = s_w[k];
            const float* xr = g_xh + (size_t)s_src[k] * 512;
            acc0 += wv.x * xr[c];
            acc1 += wv.y * xr[c + 128];
            acc2 += wv.z * xr[c + 256];
            acc3 += wv.w * xr[c + 384];
        }
        __syncthreads();
    }
    float r = 0.25f * (acc0 / s_z[0] + acc1 / s_z[1] + acc2 / s_z[2] + acc3 / s_z[3]) + bconv[c];
    r = fmaxf(r, 0.f);
    g_h[(size_t)n * HID + c] += r;   // h still holds the residual
}

// ---------------- output projection ----------------
__global__ void k_out_proj(const float* __restrict__ W, const float* __restrict__ b,
                           float* __restrict__ out) {
    int n = blockIdx.x;
    __shared__ float sh[128];
    int t = threadIdx.x;  // 64
    sh[t] = g_h[(size_t)n * 128 + t];
    sh[t + 64] = g_h[(size_t)n * 128 + 64 + t];
    __syncthreads();
    float s = b[t];
#pragma unroll
    for (int k = 0; k < 128; k++) s += sh[k] * W[k * 64 + t];
    out[(size_t)n * 64 + t] = s;
}

// ---------------- launch ----------------
extern "C" void kernel_launch(void* const* d_in, const int* in_sizes, int n_in,
                              void* d_out, int out_size) {
    const float* x       = (const float*)d_in[0];
    const int*   ei      = (const int*)d_in[1];
    const float* W_in    = (const float*)d_in[2];
    const float* b_in    = (const float*)d_in[3];
    const float* W_conv  = (const float*)d_in[4];
    const float* att_src = (const float*)d_in[5];
    const float* att_dst = (const float*)d_in[6];
    const float* b_conv  = (const float*)d_in[7];
    const float* ln_g    = (const float*)d_in[8];
    const float* ln_b    = (const float*)d_in[9];
    const float* W_out   = (const float*)d_in[10];
    const float* b_out   = (const float*)d_in[11];
    float* out = (float*)d_out;

    // CSR build (recomputed each launch; deterministic up to fp-harmless ordering)
    k_zero_cnt<<<(NN + 255) / 256, 256>>>();
    k_count<<<(E2 + 255) / 256, 256>>>(ei);
    k_scan<<<1, 1024>>>();
    k_fill<<<(E2 + 255) / 256, 256>>>(ei);

    k_in_proj<<<(NN * HID + 255) / 256, 256>>>(x, W_in, b_in);

    dim3 lnBlk(32, 4);
    dim3 gemmGrid(512 / BN, (NN + BM - 1) / BM);
    for (int i = 0; i < DEPTH; i++) {
        k_ln<<<NN / 4, lnBlk>>>(ln_g + i * HID, ln_b + i * HID);
        k_gemm<<<gemmGrid, 256>>>(W_conv + (size_t)i * HID * HEADS * HID);
        k_attn<<<NN, 128>>>(att_src + (size_t)i * HEADS * HID,
                            att_dst + (size_t)i * HEADS * HID);
        k_agg<<<NN, 128>>>(b_conv + i * HID);
    }

    k_out_proj<<<NN, 64>>>(W_out, b_out, out);
}

// round 3
// speedup vs baseline: 1.7125x; 1.7125x over previous
#include <cuda_runtime.h>
#include <cuda_fp16.h>
#include <cstdint>
#include <math.h>

#define NN 50000
#define EE 800000
#define E2 (EE + NN)
#define HID 128
#define HEADS 4
#define OUTC 64
#define DEPTH 4
#define FEPS 1e-6f
#define NEG_SLOPE 0.2f

// ---------------- device scratch ----------------
__device__ float  g_h[(size_t)NN * HID];
__device__ float  g_ln[(size_t)NN * HID];
__device__ __half g_xh[(size_t)NN * HEADS * HID];  // 51.2 MB, L2-resident
__device__ float  g_as[(size_t)NN * HEADS];
__device__ float  g_ad[(size_t)NN * HEADS];
__device__ int    g_cnt[NN];
__device__ int    g_rowptr[NN + 1];
__device__ int    g_wp[NN];
__device__ int    g_src[E2];
__device__ int    g_bsum[64];
__device__ int    g_boff[64];

// ---------------- CSR build ----------------
__global__ void k_zero_cnt() {
    int i = blockIdx.x * blockDim.x + threadIdx.x;
    if (i < NN) g_cnt[i] = 0;
}
__device__ __forceinline__ int edge_src(const int* ei, int e) { return (e < EE) ? ei[e] : (e - EE); }
__device__ __forceinline__ int edge_dst(const int* ei, int e) { return (e < EE) ? ei[EE + e] : (e - EE); }

__global__ void k_count(const int* __restrict__ ei) {
    int e = blockIdx.x * blockDim.x + threadIdx.x;
    if (e < E2) atomicAdd(&g_cnt[edge_dst(ei, e)], 1);
}

// block-level exclusive scan (49 blocks x 1024)
__global__ void k_scan1() {
    __shared__ int sh[1024];
    int tid = threadIdx.x;
    int i = blockIdx.x * 1024 + tid;
    int v = (i < NN) ? g_cnt[i] : 0;
    sh[tid] = v;
    __syncthreads();
    for (int off = 1; off < 1024; off <<= 1) {
        int t = (tid >= off) ? sh[tid - off] : 0;
        __syncthreads();
        sh[tid] += t;
        __syncthreads();
    }
    if (i < NN) g_rowptr[i] = sh[tid] - v;
    if (tid == 1023) g_bsum[blockIdx.x] = sh[1023];
}
__global__ void k_scan2(int nblk) {  // 1 block, 64 threads
    __shared__ int sh[64];
    int tid = threadIdx.x;
    sh[tid] = (tid < nblk) ? g_bsum[tid] : 0;
    __syncthreads();
    if (tid == 0) {
        int acc = 0;
        for (int b = 0; b < nblk; b++) { g_boff[b] = acc; acc += sh[b]; }
        g_rowptr[NN] = acc;
    }
}
__global__ void k_scan3() {
    int i = blockIdx.x * blockDim.x + threadIdx.x;
    if (i < NN) {
        int r = g_rowptr[i] + g_boff[i >> 10];
        g_rowptr[i] = r;
        g_wp[i] = r;
    }
}
__global__ void k_fill(const int* __restrict__ ei) {
    int e = blockIdx.x * blockDim.x + threadIdx.x;
    if (e < E2) {
        int d = edge_dst(ei, e);
        int s = edge_src(ei, e);
        int pos = atomicAdd(&g_wp[d], 1);
        g_src[pos] = s;
    }
}

// ---------------- input projection ----------------
__global__ void k_in_proj(const float* __restrict__ x, const float* __restrict__ Win,
                          const float* __restrict__ bin) {
    int i = blockIdx.x * blockDim.x + threadIdx.x;
    if (i >= NN * HID) return;
    int n = i >> 7, c = i & 127;
    float x0 = x[n * 3 + 0], x1 = x[n * 3 + 1], x2 = x[n * 3 + 2];
    g_h[i] = x0 * Win[c] + x1 * Win[HID + c] + x2 * Win[2 * HID + c] + bin[c];
}

// ---------------- layer norm ----------------
__global__ void k_ln(const float* __restrict__ gamma, const float* __restrict__ beta) {
    int row = blockIdx.x * 4 + threadIdx.y;
    if (row >= NN) return;
    int lane = threadIdx.x;
    const float* hr = g_h + (size_t)row * HID;
    float v0 = hr[lane], v1 = hr[lane + 32], v2 = hr[lane + 64], v3 = hr[lane + 96];
    float s = v0 + v1 + v2 + v3;
#pragma unroll
    for (int o = 16; o; o >>= 1) s += __shfl_xor_sync(0xffffffffu, s, o);
    float mu = s * (1.0f / 128.0f);
    float d0 = v0 - mu, d1 = v1 - mu, d2 = v2 - mu, d3 = v3 - mu;
    float q = d0 * d0 + d1 * d1 + d2 * d2 + d3 * d3;
#pragma unroll
    for (int o = 16; o; o >>= 1) q += __shfl_xor_sync(0xffffffffu, q, o);
    float inv = rsqrtf(q * (1.0f / 128.0f) + FEPS);
    float* lr = g_ln + (size_t)row * HID;
    lr[lane]      = d0 * inv * gamma[lane]      + beta[lane];
    lr[lane + 32] = d1 * inv * gamma[lane + 32] + beta[lane + 32];
    lr[lane + 64] = d2 * inv * gamma[lane + 64] + beta[lane + 64];
    lr[lane + 96] = d3 * inv * gamma[lane + 96] + beta[lane + 96];
}

// ---------------- tensor-core GEMM: ln[N,128] @ W[128,512] -> xh fp16 ----------------
// block tile 128x64, 8 warps (4x2) each 32x32, mma.m16n8k16 fp16->fp32
#define BKG 64
#define ASTR 72   // padded halfs per row (144 B -> conflict-free LDSM)

__device__ __forceinline__ void ldsm_x4(unsigned* r, unsigned addr) {
    asm volatile("ldmatrix.sync.aligned.m8n8.x4.shared.b16 {%0,%1,%2,%3}, [%4];"
                 : "=r"(r[0]), "=r"(r[1]), "=r"(r[2]), "=r"(r[3]) : "r"(addr));
}
__device__ __forceinline__ void ldsm_x2(unsigned* r, unsigned addr) {
    asm volatile("ldmatrix.sync.aligned.m8n8.x2.shared.b16 {%0,%1}, [%2];"
                 : "=r"(r[0]), "=r"(r[1]) : "r"(addr));
}
__device__ __forceinline__ void mma16816(float* c, const unsigned* a, const unsigned* b) {
    asm volatile("mma.sync.aligned.m16n8k16.row.col.f32.f16.f16.f32 "
                 "{%0,%1,%2,%3}, {%4,%5,%6,%7}, {%8,%9}, {%0,%1,%2,%3};"
                 : "+f"(c[0]), "+f"(c[1]), "+f"(c[2]), "+f"(c[3])
                 : "r"(a[0]), "r"(a[1]), "r"(a[2]), "r"(a[3]), "r"(b[0]), "r"(b[1]));
}

__global__ __launch_bounds__(256, 2) void k_gemm(const float* __restrict__ W) {
    __shared__ __half SA[128 * ASTR];   // A: [row][k]
    __shared__ __half SB[64 * ASTR];    // B^T: [n][k]
    int tid = threadIdx.x;
    int row0 = blockIdx.y * 128;
    int col0 = blockIdx.x * 64;
    int wid = tid >> 5, lane = tid & 31;
    int wm = wid & 3, wn = wid >> 2;        // warp tile: rows wm*32, cols wn*32
    int g = lane >> 2, tq = lane & 3;

    float acc[2][4][4];
#pragma unroll
    for (int i = 0; i < 2; i++)
#pragma unroll
        for (int j = 0; j < 4; j++)
#pragma unroll
            for (int q = 0; q < 4; q++) acc[i][j][q] = 0.f;

    unsigned sa_base = (unsigned)__cvta_generic_to_shared(SA);
    unsigned sb_base = (unsigned)__cvta_generic_to_shared(SB);

    for (int k0 = 0; k0 < 128; k0 += BKG) {
        // stage A: 128 rows x 64 k (fp32 -> fp16)
#pragma unroll
        for (int l = 0; l < 8; l++) {
            int idx = tid + l * 256;            // 2048 float4 slots
            int r = idx >> 4, c4 = (idx & 15) * 4;
            float4 v = make_float4(0.f, 0.f, 0.f, 0.f);
            if (row0 + r < NN)
                v = *(const float4*)(g_ln + (size_t)(row0 + r) * 128 + k0 + c4);
            __half2 h01 = __floats2half2_rn(v.x, v.y);
            __half2 h23 = __floats2half2_rn(v.z, v.w);
            *(__half2*)(SA + r * ASTR + c4)     = h01;
            *(__half2*)(SA + r * ASTR + c4 + 2) = h23;
        }
        // stage B^T: 64 n x 64 k
#pragma unroll
        for (int l = 0; l < 16; l++) {
            int idx = tid + l * 256;            // 4096 elems
            int kk = idx >> 6, n = idx & 63;
            float v = W[(size_t)(k0 + kk) * 512 + col0 + n];
            SB[n * ASTR + kk] = __float2half_rn(v);
        }
        __syncthreads();

#pragma unroll
        for (int ks = 0; ks < BKG; ks += 16) {
            unsigned af[2][4], bf[4][2];
            int acol = ks + ((lane >= 16) ? 8 : 0);
#pragma unroll
            for (int mf = 0; mf < 2; mf++) {
                int arow = wm * 32 + mf * 16 + (lane & 15);
                ldsm_x4(af[mf], sa_base + (arow * ASTR + acol) * 2);
            }
            int brow_k = ks + ((lane & 8) ? 8 : 0);
#pragma unroll
            for (int nf = 0; nf < 4; nf++) {
                int bn = wn * 32 + nf * 8 + (lane & 7);
                ldsm_x2(bf[nf], sb_base + (bn * ASTR + brow_k) * 2);
            }
#pragma unroll
            for (int mf = 0; mf < 2; mf++)
#pragma unroll
                for (int nf = 0; nf < 4; nf++)
                    mma16816(acc[mf][nf], af[mf], bf[nf]);
        }
        __syncthreads();
    }

    // epilogue: fp32 acc -> fp16 xh
#pragma unroll
    for (int mf = 0; mf < 2; mf++) {
#pragma unroll
        for (int nf = 0; nf < 4; nf++) {
            int col = col0 + wn * 32 + nf * 8 + tq * 2;
            int r1 = row0 + wm * 32 + mf * 16 + g;
            int r2 = r1 + 8;
            if (r1 < NN)
                *(__half2*)(g_xh + (size_t)r1 * 512 + col) =
                    __floats2half2_rn(acc[mf][nf][0], acc[mf][nf][1]);
            if (r2 < NN)
                *(__half2*)(g_xh + (size_t)r2 * 512 + col) =
                    __floats2half2_rn(acc[mf][nf][2], acc[mf][nf][3]);
        }
    }
}

// ---------------- attention scalars ----------------
__global__ void k_attn(const float* __restrict__ asrc, const float* __restrict__ adst) {
    int n = blockIdx.x;
    int w = threadIdx.x >> 5, lane = threadIdx.x & 31;
    const __half2* xr = (const __half2*)(g_xh + (size_t)n * 512 + w * 128);
    const float* av = asrc + w * 128;
    const float* dv = adst + w * 128;
    float sa = 0.f, sd = 0.f;
#pragma unroll
    for (int i = lane; i < 64; i += 32) {
        float2 v = __half22float2(xr[i]);
        sa += v.x * av[2 * i] + v.y * av[2 * i + 1];
        sd += v.x * dv[2 * i] + v.y * dv[2 * i + 1];
    }
#pragma unroll
    for (int o = 16; o; o >>= 1) {
        sa += __shfl_xor_sync(0xffffffffu, sa, o);
        sd += __shfl_xor_sync(0xffffffffu, sd, o);
    }
    if (lane == 0) { g_as[n * 4 + w] = sa; g_ad[n * 4 + w] = sd; }
}

// ---------------- aggregation: single-pass softmax + gather + fuse ----------------
#define CHUNK 256
__device__ __forceinline__ float lrelu(float x) { return x > 0.f ? x : NEG_SLOPE * x; }

__global__ void k_agg(const float* __restrict__ bconv) {
    int n = blockIdx.x;
    int t = threadIdx.x;                  // 128
    int w = t >> 5, lane = t & 31;
    int beg = g_rowptr[n], end = g_rowptr[n + 1];

    __shared__ float2 s_w[2][CHUNK];      // [head-pair][edge]
    __shared__ int    s_src[CHUNK];
    __shared__ float  s_part[2][HID];
    __shared__ float  red[4][4];
    __shared__ float  s_z[4];

    float4 adv = *(const float4*)(g_ad + (size_t)n * 4);

    int hp = t >> 6;                      // 0: heads 0,1 | 1: heads 2,3
    int c0 = (t & 63) * 2;                // channel pair
    int h0 = hp * 2;
    float z0 = 0.f, z1 = 0.f, z2 = 0.f, z3 = 0.f;
    float aA0 = 0.f, aA1 = 0.f, aB0 = 0.f, aB1 = 0.f;

    const float2* s_wp = s_w[hp];
    int xoffA = h0 * 64 + (c0 >> 1);      // half2 index for head h0
    int xoffB = xoffA + 64;               // head h0+1

    for (int cb = beg; cb < end; cb += CHUNK) {
        int ce = min(end, cb + CHUNK);
        for (int k = cb + t; k < ce; k += 128) {
            int s = g_src[k];
            float4 a = *(const float4*)(g_as + (size_t)s * 4);
            float w0 = __expf(lrelu(a.x + adv.x));
            float w1 = __expf(lrelu(a.y + adv.y));
            float w2 = __expf(lrelu(a.z + adv.z));
            float w3 = __expf(lrelu(a.w + adv.w));
            s_w[0][k - cb] = make_float2(w0, w1);
            s_w[1][k - cb] = make_float2(w2, w3);
            s_src[k - cb] = s;
            z0 += w0; z1 += w1; z2 += w2; z3 += w3;
        }
        __syncthreads();
        int cnt = ce - cb;
        for (int k = 0; k < cnt; k++) {
            float2 wv = s_wp[k];
            const __half2* xr = (const __half2*)(g_xh + (size_t)s_src[k] * 512);
            float2 xA = __half22float2(xr[xoffA]);
            float2 xB = __half22float2(xr[xoffB]);
            aA0 += wv.x * xA.x; aA1 += wv.x * xA.y;
            aB0 += wv.y * xB.x; aB1 += wv.y * xB.y;
        }
        __syncthreads();
    }

    // block-reduce z
#pragma unroll
    for (int o = 16; o; o >>= 1) {
        z0 += __shfl_xor_sync(0xffffffffu, z0, o);
        z1 += __shfl_xor_sync(0xffffffffu, z1, o);
        z2 += __shfl_xor_sync(0xffffffffu, z2, o);
        z3 += __shfl_xor_sync(0xffffffffu, z3, o);
    }
    if (lane == 0) { red[w][0] = z0; red[w][1] = z1; red[w][2] = z2; red[w][3] = z3; }
    __syncthreads();
    if (t == 0) {
#pragma unroll
        for (int h = 0; h < 4; h++)
            s_z[h] = red[0][h] + red[1][h] + red[2][h] + red[3][h];
    }
    __syncthreads();
    float iZA = 1.0f / s_z[h0], iZB = 1.0f / s_z[h0 + 1];
    s_part[hp][c0]     = aA0 * iZA + aB0 * iZB;
    s_part[hp][c0 + 1] = aA1 * iZA + aB1 * iZB;
    __syncthreads();
    float r = 0.25f * (s_part[0][t] + s_part[1][t]) + bconv[t];
    g_h[(size_t)n * HID + t] += fmaxf(r, 0.f);
}

// ---------------- output projection ----------------
__global__ void k_out_proj(const float* __restrict__ W, const float* __restrict__ b,
                           float* __restrict__ out) {
    int n = blockIdx.x;
    __shared__ float sh[128];
    int t = threadIdx.x;  // 64
    sh[t] = g_h[(size_t)n * 128 + t];
    sh[t + 64] = g_h[(size_t)n * 128 + 64 + t];
    __syncthreads();
    float s = b[t];
#pragma unroll
    for (int k = 0; k < 128; k++) s += sh[k] * W[k * 64 + t];
    out[(size_t)n * 64 + t] = s;
}

// ---------------- launch ----------------
extern "C" void kernel_launch(void* const* d_in, const int* in_sizes, int n_in,
                              void* d_out, int out_size) {
    const float* x       = (const float*)d_in[0];
    const int*   ei      = (const int*)d_in[1];
    const float* W_in    = (const float*)d_in[2];
    const float* b_in    = (const float*)d_in[3];
    const float* W_conv  = (const float*)d_in[4];
    const float* att_src = (const float*)d_in[5];
    const float* att_dst = (const float*)d_in[6];
    const float* b_conv  = (const float*)d_in[7];
    const float* ln_g    = (const float*)d_in[8];
    const float* ln_b    = (const float*)d_in[9];
    const float* W_out   = (const float*)d_in[10];
    const float* b_out   = (const float*)d_in[11];
    float* out = (float*)d_out;

    int nblk = (NN + 1023) / 1024;
    k_zero_cnt<<<(NN + 255) / 256, 256>>>();
    k_count<<<(E2 + 255) / 256, 256>>>(ei);
    k_scan1<<<nblk, 1024>>>();
    k_scan2<<<1, 64>>>(nblk);
    k_scan3<<<nblk, 1024>>>();
    k_fill<<<(E2 + 255) / 256, 256>>>(ei);

    k_in_proj<<<(NN * HID + 255) / 256, 256>>>(x, W_in, b_in);

    dim3 lnBlk(32, 4);
    dim3 gemmGrid(512 / 64, (NN + 127) / 128);
    for (int i = 0; i < DEPTH; i++) {
        k_ln<<<(NN + 3) / 4, lnBlk>>>(ln_g + i * HID, ln_b + i * HID);
        k_gemm<<<gemmGrid, 256>>>(W_conv + (size_t)i * HID * HEADS * HID);
        k_attn<<<NN, 128>>>(att_src + (size_t)i * HEADS * HID,
                            att_dst + (size_t)i * HEADS * HID);
        k_agg<<<NN, 128>>>(b_conv + i * HID);
    }

    k_out_proj<<<NN, 64>>>(W_out, b_out, out);
}

// round 4
// speedup vs baseline: 2.2486x; 1.3130x over previous
#include <cuda_runtime.h>
#include <cuda_fp16.h>
#include <cstdint>
#include <math.h>

#define NN 50000
#define EE 800000
#define E2 (EE + NN)
#define HID 128
#define HEADS 4
#define OUTC 64
#define DEPTH 4
#define FEPS 1e-6f
#define NEG_SLOPE 0.2f

// ---------------- device scratch ----------------
__device__ float  g_h[(size_t)NN * HID];
__device__ __half g_lnh[(size_t)NN * HID];          // fp16 LN output
__device__ __half g_xh[(size_t)NN * HEADS * HID];   // 51.2 MB, L2-resident
__device__ float  g_as[(size_t)NN * HEADS];
__device__ float  g_ad[(size_t)NN * HEADS];
__device__ int    g_cnt[NN];
__device__ int    g_rowptr[NN + 1];
__device__ int    g_wp[NN];
__device__ int    g_src[E2];
__device__ int    g_bsum[64];
__device__ int    g_boff[64];

// ---------------- CSR build ----------------
__global__ void k_zero_cnt() {
    int i = blockIdx.x * blockDim.x + threadIdx.x;
    if (i < NN) g_cnt[i] = 0;
}
__device__ __forceinline__ int edge_src(const int* ei, int e) { return (e < EE) ? ei[e] : (e - EE); }
__device__ __forceinline__ int edge_dst(const int* ei, int e) { return (e < EE) ? ei[EE + e] : (e - EE); }

__global__ void k_count(const int* __restrict__ ei) {
    int e = blockIdx.x * blockDim.x + threadIdx.x;
    if (e < E2) atomicAdd(&g_cnt[edge_dst(ei, e)], 1);
}
__global__ void k_scan1() {
    __shared__ int sh[1024];
    int tid = threadIdx.x;
    int i = blockIdx.x * 1024 + tid;
    int v = (i < NN) ? g_cnt[i] : 0;
    sh[tid] = v;
    __syncthreads();
    for (int off = 1; off < 1024; off <<= 1) {
        int t = (tid >= off) ? sh[tid - off] : 0;
        __syncthreads();
        sh[tid] += t;
        __syncthreads();
    }
    if (i < NN) g_rowptr[i] = sh[tid] - v;
    if (tid == 1023) g_bsum[blockIdx.x] = sh[1023];
}
__global__ void k_scan2(int nblk) {
    __shared__ int sh[64];
    int tid = threadIdx.x;
    sh[tid] = (tid < nblk) ? g_bsum[tid] : 0;
    __syncthreads();
    if (tid == 0) {
        int acc = 0;
        for (int b = 0; b < nblk; b++) { g_boff[b] = acc; acc += sh[b]; }
        g_rowptr[NN] = acc;
    }
}
__global__ void k_scan3() {
    int i = blockIdx.x * blockDim.x + threadIdx.x;
    if (i < NN) {
        int r = g_rowptr[i] + g_boff[i >> 10];
        g_rowptr[i] = r;
        g_wp[i] = r;
    }
}
__global__ void k_fill(const int* __restrict__ ei) {
    int e = blockIdx.x * blockDim.x + threadIdx.x;
    if (e < E2) {
        int d = edge_dst(ei, e);
        int s = edge_src(ei, e);
        int pos = atomicAdd(&g_wp[d], 1);
        g_src[pos] = s;
    }
}

// ---------------- input projection ----------------
__global__ void k_in_proj(const float* __restrict__ x, const float* __restrict__ Win,
                          const float* __restrict__ bin) {
    int i = blockIdx.x * blockDim.x + threadIdx.x;
    if (i >= NN * HID) return;
    int n = i >> 7, c = i & 127;
    float x0 = x[n * 3 + 0], x1 = x[n * 3 + 1], x2 = x[n * 3 + 2];
    g_h[i] = x0 * Win[c] + x1 * Win[HID + c] + x2 * Win[2 * HID + c] + bin[c];
}

// ---------------- layer norm (warp per row, fp16 out) + zero as/ad ----------------
__global__ void k_ln(const float* __restrict__ gamma, const float* __restrict__ beta) {
    int row = blockIdx.x * 4 + (threadIdx.x >> 5);
    if (row >= NN) return;
    int lane = threadIdx.x & 31;
    float4 v = *(const float4*)(g_h + (size_t)row * 128 + lane * 4);
    float s = v.x + v.y + v.z + v.w;
#pragma unroll
    for (int o = 16; o; o >>= 1) s += __shfl_xor_sync(0xffffffffu, s, o);
    float mu = s * (1.0f / 128.0f);
    float d0 = v.x - mu, d1 = v.y - mu, d2 = v.z - mu, d3 = v.w - mu;
    float q = d0 * d0 + d1 * d1 + d2 * d2 + d3 * d3;
#pragma unroll
    for (int o = 16; o; o >>= 1) q += __shfl_xor_sync(0xffffffffu, q, o);
    float inv = rsqrtf(q * (1.0f / 128.0f) + FEPS);
    float4 gm = *(const float4*)(gamma + lane * 4);
    float4 bt = *(const float4*)(beta + lane * 4);
    __half2 h0 = __floats2half2_rn(d0 * inv * gm.x + bt.x, d1 * inv * gm.y + bt.y);
    __half2 h1 = __floats2half2_rn(d2 * inv * gm.z + bt.z, d3 * inv * gm.w + bt.w);
    __half2* op = (__half2*)(g_lnh + (size_t)row * 128 + lane * 4);
    op[0] = h0; op[1] = h1;
    if (lane < 4) { g_as[row * 4 + lane] = 0.f; g_ad[row * 4 + lane] = 0.f; }
}

// ---------------- tensor-core GEMM + fused attention dots ----------------
#define BKG 64
#define ASTR 72

__device__ __forceinline__ void ldsm_x4(unsigned* r, unsigned addr) {
    asm volatile("ldmatrix.sync.aligned.m8n8.x4.shared.b16 {%0,%1,%2,%3}, [%4];"
                 : "=r"(r[0]), "=r"(r[1]), "=r"(r[2]), "=r"(r[3]) : "r"(addr));
}
__device__ __forceinline__ void ldsm_x2(unsigned* r, unsigned addr) {
    asm volatile("ldmatrix.sync.aligned.m8n8.x2.shared.b16 {%0,%1}, [%2];"
                 : "=r"(r[0]), "=r"(r[1]) : "r"(addr));
}
__device__ __forceinline__ void mma16816(float* c, const unsigned* a, const unsigned* b) {
    asm volatile("mma.sync.aligned.m16n8k16.row.col.f32.f16.f16.f32 "
                 "{%0,%1,%2,%3}, {%4,%5,%6,%7}, {%8,%9}, {%0,%1,%2,%3};"
                 : "+f"(c[0]), "+f"(c[1]), "+f"(c[2]), "+f"(c[3])
                 : "r"(a[0]), "r"(a[1]), "r"(a[2]), "r"(a[3]), "r"(b[0]), "r"(b[1]));
}

__global__ __launch_bounds__(256, 2) void k_gemm(const float* __restrict__ W,
                                                 const float* __restrict__ asrc,
                                                 const float* __restrict__ adst) {
    __shared__ __half SA[128 * ASTR];
    __shared__ __half SB[64 * ASTR];
    int tid = threadIdx.x;
    int row0 = blockIdx.y * 128;
    int col0 = blockIdx.x * 64;
    int wid = tid >> 5, lane = tid & 31;
    int wm = wid & 3, wn = wid >> 2;
    int g = lane >> 2, tq = lane & 3;

    float acc[2][4][4];
#pragma unroll
    for (int i = 0; i < 2; i++)
#pragma unroll
        for (int j = 0; j < 4; j++)
#pragma unroll
            for (int q = 0; q < 4; q++) acc[i][j][q] = 0.f;

    unsigned sa_base = (unsigned)__cvta_generic_to_shared(SA);
    unsigned sb_base = (unsigned)__cvta_generic_to_shared(SB);

    for (int k0 = 0; k0 < 128; k0 += BKG) {
        // stage A (fp16 direct copy): 128 rows x 64 k = 1024 uint4
#pragma unroll
        for (int l = 0; l < 4; l++) {
            int idx = tid + l * 256;
            int r = idx >> 3, c8 = (idx & 7) * 8;
            uint4 v = make_uint4(0, 0, 0, 0);
            if (row0 + r < NN)
                v = *(const uint4*)(g_lnh + (size_t)(row0 + r) * 128 + k0 + c8);
            *(uint4*)(SA + r * ASTR + c8) = v;
        }
        // stage B^T: 64 n x 64 k
#pragma unroll
        for (int l = 0; l < 16; l++) {
            int idx = tid + l * 256;
            int kk = idx >> 6, n = idx & 63;
            float v = W[(size_t)(k0 + kk) * 512 + col0 + n];
            SB[n * ASTR + kk] = __float2half_rn(v);
        }
        __syncthreads();

#pragma unroll
        for (int ks = 0; ks < BKG; ks += 16) {
            unsigned af[2][4], bf[4][2];
            int acol = ks + ((lane >= 16) ? 8 : 0);
#pragma unroll
            for (int mf = 0; mf < 2; mf++) {
                int arow = wm * 32 + mf * 16 + (lane & 15);
                ldsm_x4(af[mf], sa_base + (arow * ASTR + acol) * 2);
            }
            int brow_k = ks + ((lane & 8) ? 8 : 0);
#pragma unroll
            for (int nf = 0; nf < 4; nf++) {
                int bn = wn * 32 + nf * 8 + (lane & 7);
                ldsm_x2(bf[nf], sb_base + (bn * ASTR + brow_k) * 2);
            }
#pragma unroll
            for (int mf = 0; mf < 2; mf++)
#pragma unroll
                for (int nf = 0; nf < 4; nf++)
                    mma16816(acc[mf][nf], af[mf], bf[nf]);
        }
        __syncthreads();
    }

    // epilogue 1: store xh fp16
#pragma unroll
    for (int mf = 0; mf < 2; mf++) {
#pragma unroll
        for (int nf = 0; nf < 4; nf++) {
            int col = col0 + wn * 32 + nf * 8 + tq * 2;
            int r1 = row0 + wm * 32 + mf * 16 + g;
            int r2 = r1 + 8;
            if (r1 < NN)
                *(__half2*)(g_xh + (size_t)r1 * 512 + col) =
                    __floats2half2_rn(acc[mf][nf][0], acc[mf][nf][1]);
            if (r2 < NN)
                *(__half2*)(g_xh + (size_t)r2 * 512 + col) =
                    __floats2half2_rn(acc[mf][nf][2], acc[mf][nf][3]);
        }
    }

    // epilogue 2: partial attention dots for this 64-col slice
    int head = blockIdx.x >> 1;
    int chb = (blockIdx.x & 1) * 64 + wn * 32 + tq * 2;  // channel within head
    float aS[4][2], aD[4][2];
#pragma unroll
    for (int nf = 0; nf < 4; nf++) {
#pragma unroll
        for (int j = 0; j < 2; j++) {
            aS[nf][j] = asrc[head * 128 + chb + nf * 8 + j];
            aD[nf][j] = adst[head * 128 + chb + nf * 8 + j];
        }
    }
#pragma unroll
    for (int mf = 0; mf < 2; mf++) {
        float s1 = 0.f, d1 = 0.f, s2 = 0.f, d2 = 0.f;
#pragma unroll
        for (int nf = 0; nf < 4; nf++) {
            s1 += acc[mf][nf][0] * aS[nf][0] + acc[mf][nf][1] * aS[nf][1];
            d1 += acc[mf][nf][0] * aD[nf][0] + acc[mf][nf][1] * aD[nf][1];
            s2 += acc[mf][nf][2] * aS[nf][0] + acc[mf][nf][3] * aS[nf][1];
            d2 += acc[mf][nf][2] * aD[nf][0] + acc[mf][nf][3] * aD[nf][1];
        }
        // reduce over tq quad (lanes xor 1, 2)
#pragma unroll
        for (int o = 1; o <= 2; o <<= 1) {
            s1 += __shfl_xor_sync(0xffffffffu, s1, o);
            d1 += __shfl_xor_sync(0xffffffffu, d1, o);
            s2 += __shfl_xor_sync(0xffffffffu, s2, o);
            d2 += __shfl_xor_sync(0xffffffffu, d2, o);
        }
        if (tq == 0) {
            int r1 = row0 + wm * 32 + mf * 16 + g;
            int r2 = r1 + 8;
            if (r1 < NN) {
                atomicAdd(&g_as[r1 * 4 + head], s1);
                atomicAdd(&g_ad[r1 * 4 + head], d1);
            }
            if (r2 < NN) {
                atomicAdd(&g_as[r2 * 4 + head], s2);
                atomicAdd(&g_ad[r2 * 4 + head], d2);
            }
        }
    }
}

// ---------------- aggregation: warp-per-head, 8B loads ----------------
#define CHUNK 256
__device__ __forceinline__ float lrelu(float x) { return x > 0.f ? x : NEG_SLOPE * x; }

__global__ void k_agg(const float* __restrict__ bconv) {
    int n = blockIdx.x;
    int t = threadIdx.x;                  // 128
    int h = t >> 5, lane = t & 31;
    int ch0 = lane * 4;
    int beg = g_rowptr[n], end = g_rowptr[n + 1];

    __shared__ float s_wf[4][CHUNK];
    __shared__ int   s_src[CHUNK];
    __shared__ float s_part[4][HID];
    __shared__ float red[4][4];
    __shared__ float s_z[4];

    float4 adv = *(const float4*)(g_ad + (size_t)n * 4);

    float z0 = 0.f, z1 = 0.f, z2 = 0.f, z3 = 0.f;
    float a0 = 0.f, a1 = 0.f, a2 = 0.f, a3 = 0.f;

    const __half* xbase = g_xh + h * 128 + ch0;

    for (int cb = beg; cb < end; cb += CHUNK) {
        int ce = min(end, cb + CHUNK);
        for (int k = cb + t; k < ce; k += 128) {
            int s = g_src[k];
            float4 a = *(const float4*)(g_as + (size_t)s * 4);
            float w0 = __expf(lrelu(a.x + adv.x));
            float w1 = __expf(lrelu(a.y + adv.y));
            float w2 = __expf(lrelu(a.z + adv.z));
            float w3 = __expf(lrelu(a.w + adv.w));
            s_wf[0][k - cb] = w0;
            s_wf[1][k - cb] = w1;
            s_wf[2][k - cb] = w2;
            s_wf[3][k - cb] = w3;
            s_src[k - cb] = s;
            z0 += w0; z1 += w1; z2 += w2; z3 += w3;
        }
        __syncthreads();
        int cnt = ce - cb;
#pragma unroll 4
        for (int k = 0; k < cnt; k++) {
            float wv = s_wf[h][k];
            uint2 u = *(const uint2*)(xbase + (size_t)s_src[k] * 512);
            float2 f0 = __half22float2(*(__half2*)&u.x);
            float2 f1 = __half22float2(*(__half2*)&u.y);
            a0 += wv * f0.x; a1 += wv * f0.y;
            a2 += wv * f1.x; a3 += wv * f1.y;
        }
        __syncthreads();
    }

    // block-reduce z
#pragma unroll
    for (int o = 16; o; o >>= 1) {
        z0 += __shfl_xor_sync(0xffffffffu, z0, o);
        z1 += __shfl_xor_sync(0xffffffffu, z1, o);
        z2 += __shfl_xor_sync(0xffffffffu, z2, o);
        z3 += __shfl_xor_sync(0xffffffffu, z3, o);
    }
    if (lane == 0) { red[h][0] = z0; red[h][1] = z1; red[h][2] = z2; red[h][3] = z3; }
    __syncthreads();
    if (t == 0) {
#pragma unroll
        for (int hh = 0; hh < 4; hh++)
            s_z[hh] = red[0][hh] + red[1][hh] + red[2][hh] + red[3][hh];
    }
    __syncthreads();
    float iz = 1.0f / s_z[h];
    *(float4*)(&s_part[h][ch0]) = make_float4(a0 * iz, a1 * iz, a2 * iz, a3 * iz);
    __syncthreads();
    float r = 0.25f * (s_part[0][t] + s_part[1][t] + s_part[2][t] + s_part[3][t]) + bconv[t];
    g_h[(size_t)n * HID + t] += fmaxf(r, 0.f);
}

// ---------------- output projection ----------------
__global__ void k_out_proj(const float* __restrict__ W, const float* __restrict__ b,
                           float* __restrict__ out) {
    int n = blockIdx.x;
    __shared__ float sh[128];
    int t = threadIdx.x;  // 64
    sh[t] = g_h[(size_t)n * 128 + t];
    sh[t + 64] = g_h[(size_t)n * 128 + 64 + t];
    __syncthreads();
    float s = b[t];
#pragma unroll
    for (int k = 0; k < 128; k++) s += sh[k] * W[k * 64 + t];
    out[(size_t)n * 64 + t] = s;
}

// ---------------- launch ----------------
extern "C" void kernel_launch(void* const* d_in, const int* in_sizes, int n_in,
                              void* d_out, int out_size) {
    const float* x       = (const float*)d_in[0];
    const int*   ei      = (const int*)d_in[1];
    const float* W_in    = (const float*)d_in[2];
    const float* b_in    = (const float*)d_in[3];
    const float* W_conv  = (const float*)d_in[4];
    const float* att_src = (const float*)d_in[5];
    const float* att_dst = (const float*)d_in[6];
    const float* b_conv  = (const float*)d_in[7];
    const float* ln_g    = (const float*)d_in[8];
    const float* ln_b    = (const float*)d_in[9];
    const float* W_out   = (const float*)d_in[10];
    const float* b_out   = (const float*)d_in[11];
    float* out = (float*)d_out;

    int nblk = (NN + 1023) / 1024;
    k_zero_cnt<<<(NN + 255) / 256, 256>>>();
    k_count<<<(E2 + 255) / 256, 256>>>(ei);
    k_scan1<<<nblk, 1024>>>();
    k_scan2<<<1, 64>>>(nblk);
    k_scan3<<<nblk, 1024>>>();
    k_fill<<<(E2 + 255) / 256, 256>>>(ei);

    k_in_proj<<<(NN * HID + 255) / 256, 256>>>(x, W_in, b_in);

    dim3 gemmGrid(512 / 64, (NN + 127) / 128);
    for (int i = 0; i < DEPTH; i++) {
        k_ln<<<(NN + 3) / 4, 128>>>(ln_g + i * HID, ln_b + i * HID);
        k_gemm<<<gemmGrid, 256>>>(W_conv + (size_t)i * HID * HEADS * HID,
                                  att_src + (size_t)i * HEADS * HID,
                                  att_dst + (size_t)i * HEADS * HID);
        k_agg<<<NN, 128>>>(b_conv + i * HID);
    }

    k_out_proj<<<NN, 64>>>(W_out, b_out, out);
}